// round 9
// baseline (speedup 1.0000x reference)
#include <cuda_runtime.h>

// SSM S4 diagonal scan: L=8192, C=512, N=64.
// u[t] = Abar*u[t-1] + x[t] (rescaled), y[t] = sum_n (C*Bbar)[n] * u[t,n]
// 3-pass chunked scan; f32x2 FMAs; transposed smem x tiles; 4x4 shfl
// sum-transpose; in-place y. This round: k_init restored (lean register
// prologues), launch_bounds raised for 9/8 resident blocks per SM.

#define LT   8192
#define CH   512
#define NS   64
#define BCH  128          // chunk length
#define NP   (LT / BCH)   // 64 chunks
#define CPB  32           // channels per block
#define XPAD 132          // row stride (floats): conflict-free
#define DT   (1.0f / 4096.0f)

typedef unsigned long long ull;

__device__ __align__(16) float g_a[NS];    // Abar
__device__ __align__(16) float g_w[NS];    // C * Bbar
__device__ __align__(16) float g_aB[NS];   // Abar^BCH
__device__ __align__(16) float g_Hl[(size_t)NP * CH * NS];   // chunk-local final states
__device__ __align__(16) float g_Hin[(size_t)NP * CH * NS];  // carry-in per chunk

// ---- packed f32x2 helpers -------------------------------------------------
__device__ __forceinline__ ull f2fma(ull a, ull b, ull c) {
    ull d; asm("fma.rn.f32x2 %0,%1,%2,%3;" : "=l"(d) : "l"(a), "l"(b), "l"(c)); return d;
}
__device__ __forceinline__ ull f2mul(ull a, ull b) {
    ull d; asm("mul.rn.f32x2 %0,%1,%2;" : "=l"(d) : "l"(a), "l"(b)); return d;
}
__device__ __forceinline__ ull f2add(ull a, ull b) {
    ull d; asm("add.rn.f32x2 %0,%1,%2;" : "=l"(d) : "l"(a), "l"(b)); return d;
}
__device__ __forceinline__ ull f2bcast(float f) {
    ull r; asm("mov.b64 %0,{%1,%1};" : "=l"(r) : "f"(f)); return r;
}
__device__ __forceinline__ float f2hsum(ull v) {
    float lo, hi; asm("mov.b64 {%0,%1},%2;" : "=f"(lo), "=f"(hi) : "l"(v));
    return lo + hi;
}

// ---- init: all coefficients in one place ----------------------------------
__global__ void k_init(const float* __restrict__ logA,
                       const float* __restrict__ Bp,
                       const float* __restrict__ Cp) {
    int n = threadIdx.x;
    if (n < NS) {
        float A    = -expf(logA[n]);           // mirror reference fp32 ops
        float Abar = expf(A * DT);
        float Bbar = (Abar - 1.0f) * Bp[n] / A;
        g_a[n] = Abar;
        g_w[n] = Cp[n] * Bbar;
        double p = 1.0, ad = (double)Abar;
        #pragma unroll 1
        for (int i = 0; i < BCH; i++) p *= ad;
        g_aB[n] = (float)p;
    }
}

// ---- K1: local scan (zero init), store chunk-final states -----------------
__global__ __launch_bounds__(128, 9) void k_local(const float* __restrict__ x) {
    __shared__ float xs[CPB][XPAD];
    const int p   = blockIdx.x;
    const int c0  = blockIdx.y * CPB;
    const int tid = threadIdx.x;

    for (int i = tid; i < BCH * (CPB / 4); i += 128) {
        int q = i & 7, j = i >> 3;
        float4 v = *(const float4*)&x[(size_t)(p * BCH + j) * CH + c0 + q * 4];
        xs[q * 4 + 0][j] = v.x; xs[q * 4 + 1][j] = v.y;
        xs[q * 4 + 2][j] = v.z; xs[q * 4 + 3][j] = v.w;
    }

    const int g  = tid & 3;       // state group (16 states = 8 f32x2 pairs)
    const int cl = tid >> 2;      // channel within block (0..31)

    ull a2[8], u2[8];
    const ull* ga2 = (const ull*)g_a;
    #pragma unroll
    for (int k = 0; k < 8; k++) { a2[k] = ga2[g * 8 + k]; u2[k] = 0ull; }
    __syncthreads();

    float4 xv = *(const float4*)&xs[cl][0];
    #pragma unroll 4
    for (int jb = 0; jb < BCH; jb += 4) {
        float4 cur = xv;
        int jn = (jb + 4 < BCH) ? jb + 4 : 0;
        xv = *(const float4*)&xs[cl][jn];        // prefetch next block
        ull xx0 = f2bcast(cur.x), xx1 = f2bcast(cur.y);
        ull xx2 = f2bcast(cur.z), xx3 = f2bcast(cur.w);
        #pragma unroll
        for (int k = 0; k < 8; k++) u2[k] = f2fma(a2[k], u2[k], xx0);
        #pragma unroll
        for (int k = 0; k < 8; k++) u2[k] = f2fma(a2[k], u2[k], xx1);
        #pragma unroll
        for (int k = 0; k < 8; k++) u2[k] = f2fma(a2[k], u2[k], xx2);
        #pragma unroll
        for (int k = 0; k < 8; k++) u2[k] = f2fma(a2[k], u2[k], xx3);
    }

    ull* dst = (ull*)&g_Hl[((size_t)p * CH + (c0 + cl)) * NS + g * 16];
    #pragma unroll
    for (int k = 0; k < 8; k++) dst[k] = u2[k];
}

// ---- K2: carry scan across chunks (pairs of states) -----------------------
__global__ __launch_bounds__(128) void k_scan() {
    int idx = blockIdx.x * blockDim.x + threadIdx.x;   // pair index: c*32 + np
    if (idx >= CH * NS / 2) return;
    int np = idx & 31;
    ull aB2 = ((const ull*)g_aB)[np];
    ull S = 0ull;
    const ull* Hl  = (const ull*)g_Hl;
    ull*       Hin = (ull*)g_Hin;
    const int stride = CH * NS / 2;
    #pragma unroll 8
    for (int p = 0; p < NP; p++) {
        Hin[(size_t)p * stride + idx] = S;
        S = f2fma(aB2, S, Hl[(size_t)p * stride + idx]);
    }
}

// ---- K3: seeded scan, emit y ----------------------------------------------
__global__ __launch_bounds__(128, 8) void k_final(const float* __restrict__ x,
                                                  float* __restrict__ y) {
    __shared__ float xs[CPB][XPAD];
    const int p   = blockIdx.x;
    const int c0  = blockIdx.y * CPB;
    const int tid = threadIdx.x;

    for (int i = tid; i < BCH * (CPB / 4); i += 128) {
        int q = i & 7, j = i >> 3;
        float4 v = *(const float4*)&x[(size_t)(p * BCH + j) * CH + c0 + q * 4];
        xs[q * 4 + 0][j] = v.x; xs[q * 4 + 1][j] = v.y;
        xs[q * 4 + 2][j] = v.z; xs[q * 4 + 3][j] = v.w;
    }

    const int g  = tid & 3;
    const int cl = tid >> 2;

    ull a2[8], w2[8], u2[8];
    const ull* ga2 = (const ull*)g_a;
    const ull* gw2 = (const ull*)g_w;
    const ull* hin = (const ull*)&g_Hin[((size_t)p * CH + (c0 + cl)) * NS + g * 16];
    #pragma unroll
    for (int k = 0; k < 8; k++) {
        a2[k] = ga2[g * 8 + k];
        w2[k] = gw2[g * 8 + k];
        u2[k] = hin[k];
    }
    __syncthreads();

    float4 xv = *(const float4*)&xs[cl][0];
    #pragma unroll 2
    for (int jb = 0; jb < BCH; jb += 4) {
        float4 cur = xv;
        int jn = (jb + 4 < BCH) ? jb + 4 : 0;
        xv = *(const float4*)&xs[cl][jn];        // prefetch next block
        ull xxs[4] = {f2bcast(cur.x), f2bcast(cur.y), f2bcast(cur.z), f2bcast(cur.w)};
        float pt[4];
        #pragma unroll
        for (int s = 0; s < 4; s++) {
            ull xx = xxs[s];
            #pragma unroll
            for (int k = 0; k < 8; k++) u2[k] = f2fma(a2[k], u2[k], xx);
            ull s0 = f2mul(w2[0], u2[0]);
            ull s1 = f2mul(w2[1], u2[1]);
            #pragma unroll
            for (int k = 2; k < 8; k += 2) {
                s0 = f2fma(w2[k],     u2[k],     s0);
                s1 = f2fma(w2[k + 1], u2[k + 1], s1);
            }
            pt[s] = f2hsum(f2add(s0, s1));
        }
        // 4x4 sum-transpose across the quad: lane g ends with total for jb+g.
        float p0 = pt[0], p1 = pt[1], p2 = pt[2], p3 = pt[3];
        float send1 = (g & 1) ? p0 : p1;
        float r1 = __shfl_xor_sync(0xffffffffu, send1, 1);
        if (g & 1) p1 += r1; else p0 += r1;
        float send2 = (g & 1) ? p2 : p3;
        float r2 = __shfl_xor_sync(0xffffffffu, send2, 1);
        if (g & 1) p3 += r2; else p2 += r2;
        float send3 = (g & 2) ? ((g & 1) ? p1 : p0) : ((g & 1) ? p3 : p2);
        float r3 = __shfl_xor_sync(0xffffffffu, send3, 2);
        float total = ((g & 1) ? ((g & 2) ? p3 : p1) : ((g & 2) ? p2 : p0)) + r3;
        xs[cl][jb + g] = total;                  // in-place y
    }
    __syncthreads();

    for (int i = tid; i < BCH * (CPB / 4); i += 128) {
        int q = i & 7, j = i >> 3;
        float4 v = make_float4(xs[q * 4 + 0][j], xs[q * 4 + 1][j],
                               xs[q * 4 + 2][j], xs[q * 4 + 3][j]);
        *(float4*)&y[(size_t)(p * BCH + j) * CH + c0 + q * 4] = v;
    }
}

extern "C" void kernel_launch(void* const* d_in, const int* in_sizes, int n_in,
                              void* d_out, int out_size) {
    const float* x    = (const float*)d_in[0];
    const float* logA = (const float*)d_in[1];
    const float* Bp   = (const float*)d_in[2];
    const float* Cp   = (const float*)d_in[3];
    float* y = (float*)d_out;

    k_init<<<1, 64>>>(logA, Bp, Cp);
    dim3 grid(NP, CH / CPB);                 // 64 x 16 = 1024 blocks
    k_local<<<grid, 128>>>(x);
    k_scan<<<(CH * NS / 2) / 128, 128>>>();
    k_final<<<grid, 128>>>(x, y);
}